// round 9
// baseline (speedup 1.0000x reference)
#include <cuda_runtime.h>
#include <cuda_fp16.h>
#include <cstdint>

// ---------------- problem constants ----------------
#define B_ROWS 16384
#define DIN 512
#define DOUT 512
#define NE 8
#define GCOLS 2

// ---------------- GEMM tiling ----------------
#define TM 128
#define TN 64
#define TK 32
#define NSTAGE (DIN / TK)          // 16
#define NPIPE 4
#define NCOLT (DOUT / TN)          // 8 column tiles

#define SA 40    // A smem row stride (halves): 80B, conflict-free ldmatrix
#define SBH 72   // B smem row stride (halves): 144B (16 mod 128 -> conflict-free trans)

#define AOF 0
#define BOF (TM * SA * 2)                      // 10240
#define BUF_BYTES (TM * SA * 2 + TK * SBH * 2) // 14848
#define OFF_BUF 1024
#define GEMM_SMEM (OFF_BUF + NPIPE * BUF_BYTES)  // 60416 -> 3 CTAs/SM

#define GEMM_GRID 456   // 3 CTAs/SM x 152 SMs, all co-resident

// ---------------- device scratch ----------------
__device__ int g_fill[NE];       // zero at start; self-reset by gemm
__device__ int g_work;
__device__ int g_done;
__device__ int g_rowpad[NE * B_ROWS];

__device__ __align__(16) __half g_xh[B_ROWS * DIN];      // 16MB
__device__ __align__(16) __half g_wh[NE * DIN * DOUT];   // 4MB, [e][k][n]

// ---------------- helpers ----------------
__device__ __forceinline__ uint32_t smem_u32(const void* p) {
    uint32_t a;
    asm("{ .reg .u64 t; cvta.to.shared.u64 t, %1; cvt.u32.u64 %0, t; }" : "=r"(a) : "l"(p));
    return a;
}
__device__ __forceinline__ void ldsm_x4(uint32_t* r, uint32_t addr) {
    asm volatile("ldmatrix.sync.aligned.m8n8.x4.shared.b16 {%0,%1,%2,%3}, [%4];"
                 : "=r"(r[0]), "=r"(r[1]), "=r"(r[2]), "=r"(r[3]) : "r"(addr));
}
__device__ __forceinline__ void ldsm_x4_t(uint32_t* r, uint32_t addr) {
    asm volatile("ldmatrix.sync.aligned.m8n8.x4.trans.shared.b16 {%0,%1,%2,%3}, [%4];"
                 : "=r"(r[0]), "=r"(r[1]), "=r"(r[2]), "=r"(r[3]) : "r"(addr));
}
__device__ __forceinline__ void mma_f16(float* c, const uint32_t* a, const uint32_t* b) {
    asm volatile(
        "mma.sync.aligned.m16n8k16.row.col.f32.f16.f16.f32 "
        "{%0,%1,%2,%3}, {%4,%5,%6,%7}, {%8,%9}, {%0,%1,%2,%3};"
        : "+f"(c[0]), "+f"(c[1]), "+f"(c[2]), "+f"(c[3])
        : "r"(a[0]), "r"(a[1]), "r"(a[2]), "r"(a[3]), "r"(b[0]), "r"(b[1]));
}
#define CP_ASYNC16(saddr, gaddr) \
    asm volatile("cp.async.cg.shared.global [%0], [%1], 16;" :: "r"(saddr), "l"(gaddr))
#define CP_COMMIT() asm volatile("cp.async.commit_group;")
#define CP_WAIT(n)  asm volatile("cp.async.wait_group %0;" :: "n"(n) : "memory")

// ---------------- fused prep: cvt x, cvt W, scatter ----------------
#define XBLOCKS (B_ROWS * DIN / 4 / 256)       // 8192
#define WBLOCKS (NE * DIN * DOUT / 4 / 256)    // 2048
#define SBLOCKS (B_ROWS / 256)                 // 64
#define PREP_GRID (XBLOCKS + WBLOCKS + SBLOCKS)

__global__ void prep_kernel(const float* __restrict__ x, const float* __restrict__ W,
                            const int* __restrict__ groups) {
    int bid = blockIdx.x;
    if (bid < XBLOCKS + WBLOCKS) {
        const float4* src;
        uint2* dst;
        int i;
        if (bid < XBLOCKS) {
            i = bid * blockDim.x + threadIdx.x;
            src = (const float4*)x;
            dst = (uint2*)g_xh;
        } else {
            i = (bid - XBLOCKS) * blockDim.x + threadIdx.x;
            src = (const float4*)W;
            dst = (uint2*)g_wh;
        }
        float4 v = src[i];
        __half2 h0 = __floats2half2_rn(v.x, v.y);
        __half2 h1 = __floats2half2_rn(v.z, v.w);
        dst[i] = make_uint2(*(uint32_t*)&h0, *(uint32_t*)&h1);
    } else {
        int b = (bid - XBLOCKS - WBLOCKS) * blockDim.x + threadIdx.x;
        int e = groups[b * GCOLS];
        int lane = threadIdx.x & 31;
        unsigned mask = __match_any_sync(0xffffffffu, e);
        int leader = __ffs(mask) - 1;
        int prefix = __popc(mask & ((1u << lane) - 1));
        int base = 0;
        if (lane == leader) base = atomicAdd(&g_fill[e], __popc(mask));
        base = __shfl_sync(0xffffffffu, base, leader);
        g_rowpad[e * B_ROWS + base + prefix] = b;
    }
}

// ---------------- persistent grouped GEMM: fp16, 128x64 tile, 3 CTAs/SM ----------------
__global__ __launch_bounds__(256, 3)
void gemm_mma(const float* __restrict__ bias, float* __restrict__ out) {
    extern __shared__ char sm[];
    int* sm_w   = (int*)sm;
    int* s_cum  = (int*)(sm + 16);
    int* s_fill = (int*)(sm + 64);
    int* srows  = (int*)(sm + 256);
    const uint32_t smu = smem_u32(sm);

    const int tid  = threadIdx.x;
    const int lane = tid & 31;
    const int wid  = tid >> 5;

    if (tid < NE) s_fill[tid] = g_fill[tid];
    __syncthreads();
    if (tid == 0) {
        int c = 0;
        s_cum[0] = 0;
        for (int e = 0; e < NE; e++) {
            c += (s_fill[e] + TM - 1) / TM;
            s_cum[e + 1] = c;
        }
    }
    __syncthreads();
    const int nwork = s_cum[NE] * NCOLT;

    // warp compute coords: 4 M-groups x 2 N-groups, warp tile 32x32
    const int m0w = (wid >> 1) * 32;
    const int n0w = (wid & 1) * 32;
    const int lr = (lane & 7) + ((lane >> 3) & 1) * 8;
    const int lc = (lane >> 4) * 8;
    const int a_lm_base = ((m0w + lr) * SA + lc) * 2;
    const int b_lm_base = (lr * SBH + n0w + lc) * 2;

    // cp.async slot shapes: A 2 chunks/thread, B 1 chunk/thread
    const int am0  = (tid + 0)   >> 2;
    const int am1  = (tid + 256) >> 2;
    const int asec = tid & 3;
    const uint32_t asw0 = smu + OFF_BUF + AOF + am0 * (SA * 2) + asec * 16;
    const uint32_t asw1 = smu + OFF_BUF + AOF + am1 * (SA * 2) + asec * 16;
    const int bk   = tid >> 3;
    const int bsec = tid & 7;
    const uint32_t bsw = smu + OFF_BUF + BOF + bk * (SBH * 2) + bsec * 16;

    const int rl = lane >> 2;
    const int cl = (lane & 3) * 2;

    for (;;) {
        if (tid == 0) sm_w[0] = atomicAdd(&g_work, 1);
        __syncthreads();
        const int w = sm_w[0];
        if (w >= nwork) break;

        const int n0 = (w & (NCOLT - 1)) * TN;
        const int t  = w >> 3;
        int e = 0;
        while (t >= s_cum[e + 1]) e++;
        const int rowbase = (t - s_cum[e]) * TM;
        const int cnt  = s_fill[e];
        const int rows = (cnt - rowbase < TM) ? (cnt - rowbase) : TM;

        if (tid < TM) srows[tid] = (tid < rows) ? g_rowpad[e * B_ROWS + rowbase + tid] : -1;
        __syncthreads();

        int gr0 = srows[am0]; if (gr0 < 0) gr0 = 0;
        int gr1 = srows[am1]; if (gr1 < 0) gr1 = 0;
        const __half* ag0 = g_xh + (size_t)gr0 * DIN + asec * 8;
        const __half* ag1 = g_xh + (size_t)gr1 * DIN + asec * 8;
        const __half* bg  = g_wh + ((size_t)e * DIN + bk) * DOUT + n0 + bsec * 8;

        float c[2][4][4];
#pragma unroll
        for (int mt = 0; mt < 2; mt++)
#pragma unroll
            for (int nt = 0; nt < 4; nt++)
#pragma unroll
                for (int j = 0; j < 4; j++) c[mt][nt][j] = 0.f;

        // prologue
#pragma unroll
        for (int s = 0; s < NPIPE - 1; s++) {
            const uint32_t bo = s * BUF_BYTES;
            const int ka = s * TK;
            const size_t kb = (size_t)(s * TK) * DOUT;
            CP_ASYNC16(asw0 + bo, ag0 + ka);
            CP_ASYNC16(asw1 + bo, ag1 + ka);
            CP_ASYNC16(bsw + bo,  bg  + kb);
            CP_COMMIT();
        }

        int slot = 0, fslot = NPIPE - 1;
        for (int kt = 0; kt < NSTAGE; kt++) {
            CP_WAIT(NPIPE - 2);
            __syncthreads();

            if (kt + NPIPE - 1 < NSTAGE) {
                const uint32_t bo = fslot * BUF_BYTES;
                const int ka = (kt + NPIPE - 1) * TK;
                const size_t kb = (size_t)((kt + NPIPE - 1) * TK) * DOUT;
                CP_ASYNC16(asw0 + bo, ag0 + ka);
                CP_ASYNC16(asw1 + bo, ag1 + ka);
                CP_ASYNC16(bsw + bo,  bg  + kb);
            }
            CP_COMMIT();

            const uint32_t bb = smu + OFF_BUF + slot * BUF_BYTES;
#pragma unroll
            for (int ks = 0; ks < 2; ks++) {
                const int kso = ks * 16;
                uint32_t ah[2][4];
#pragma unroll
                for (int mt = 0; mt < 2; mt++)
                    ldsm_x4(ah[mt], bb + a_lm_base + (mt * 16 * SA + kso) * 2 + AOF);
                uint32_t bh[2][4];
#pragma unroll
                for (int p = 0; p < 2; p++)
                    ldsm_x4_t(bh[p], bb + b_lm_base + (kso * SBH + p * 16) * 2 + BOF);
#pragma unroll
                for (int mt = 0; mt < 2; mt++)
#pragma unroll
                    for (int p = 0; p < 2; p++) {
                        mma_f16(c[mt][2 * p],     ah[mt], &bh[p][0]);
                        mma_f16(c[mt][2 * p + 1], ah[mt], &bh[p][2]);
                    }
            }
            slot  = (slot  + 1 == NPIPE) ? 0 : slot + 1;
            fslot = (fslot + 1 == NPIPE) ? 0 : fslot + 1;
        }

        // epilogue
#pragma unroll
        for (int mt = 0; mt < 2; mt++) {
            const int lm0 = m0w + mt * 16 + rl;
            const int r0 = srows[lm0];
            const int r1 = srows[lm0 + 8];
#pragma unroll
            for (int nt = 0; nt < 4; nt++) {
                const int gcol = n0 + n0w + nt * 8 + cl;
                const float2 bv2 = *(const float2*)(bias + e * DOUT + gcol);
                if (r0 >= 0) {
                    float2 v = make_float2(c[mt][nt][0] + bv2.x, c[mt][nt][1] + bv2.y);
                    *(float2*)(out + (size_t)r0 * DOUT + gcol) = v;
                }
                if (r1 >= 0) {
                    float2 v = make_float2(c[mt][nt][2] + bv2.x, c[mt][nt][3] + bv2.y);
                    *(float2*)(out + (size_t)r1 * DOUT + gcol) = v;
                }
            }
        }
    }

    // self-reset for next replay
    __syncthreads();
    if (tid == 0) {
        int prev = atomicAdd(&g_done, 1);
        if (prev == GEMM_GRID - 1) {
#pragma unroll
            for (int i = 0; i < NE; i++) g_fill[i] = 0;
            g_work = 0;
            g_done = 0;
            __threadfence();
        }
    }
}

// ---------------- launch ----------------
extern "C" void kernel_launch(void* const* d_in, const int* in_sizes, int n_in,
                              void* d_out, int out_size) {
    const float* x      = (const float*)d_in[0];
    const int*   groups = (const int*)d_in[1];
    const float* W      = (const float*)d_in[2];
    const float* bias   = (const float*)d_in[3];
    float*       out    = (float*)d_out;

    cudaFuncSetAttribute(gemm_mma, cudaFuncAttributeMaxDynamicSharedMemorySize, GEMM_SMEM);

    prep_kernel<<<PREP_GRID, 256>>>(x, W, groups);
    gemm_mma<<<GEMM_GRID, 256, GEMM_SMEM>>>(bias, out);
}

// round 10
// speedup vs baseline: 1.1194x; 1.1194x over previous
#include <cuda_runtime.h>
#include <cuda_fp16.h>
#include <cstdint>

// ---------------- problem constants ----------------
#define B_ROWS 16384
#define DIN 512
#define DOUT 512
#define NE 8
#define GCOLS 2

// ---------------- GEMM tiling (R7-proven config) ----------------
#define TM 128
#define TN 128
#define TK 32
#define NSTAGE (DIN / TK)          // 16
#define NPIPE 4
#define NCOLT (DOUT / TN)          // 4

#define SA 40    // A smem row stride (halves): 80B, conflict-free ldmatrix
#define SB 136   // B smem row stride (halves): 272B

#define AOF 0
#define BOF (TM * SA * 2)                     // 10240
#define BUF_BYTES (TM * SA * 2 + TK * SB * 2) // 18944
#define OFF_BUF 1024
#define GEMM_SMEM (OFF_BUF + NPIPE * BUF_BYTES)  // 76800 -> 2 CTAs/SM

#define GEMM_GRID 304   // 2 CTAs/SM x 152 SMs, all co-resident

// ---------------- device scratch ----------------
__device__ int g_fill[NE];       // zero at start; self-reset by gemm
__device__ int g_work;
__device__ int g_done;
__device__ int g_rowpad[NE * B_ROWS];

__device__ __align__(16) __half g_xh[B_ROWS * DIN];      // 16MB
__device__ __align__(16) __half g_wh[NE * DIN * DOUT];   // 4MB, [e][k][n]

// ---------------- helpers ----------------
__device__ __forceinline__ uint32_t smem_u32(const void* p) {
    uint32_t a;
    asm("{ .reg .u64 t; cvta.to.shared.u64 t, %1; cvt.u32.u64 %0, t; }" : "=r"(a) : "l"(p));
    return a;
}
__device__ __forceinline__ void ldsm_x4(uint32_t* r, uint32_t addr) {
    asm volatile("ldmatrix.sync.aligned.m8n8.x4.shared.b16 {%0,%1,%2,%3}, [%4];"
                 : "=r"(r[0]), "=r"(r[1]), "=r"(r[2]), "=r"(r[3]) : "r"(addr));
}
__device__ __forceinline__ void ldsm_x4_t(uint32_t* r, uint32_t addr) {
    asm volatile("ldmatrix.sync.aligned.m8n8.x4.trans.shared.b16 {%0,%1,%2,%3}, [%4];"
                 : "=r"(r[0]), "=r"(r[1]), "=r"(r[2]), "=r"(r[3]) : "r"(addr));
}
__device__ __forceinline__ void mma_f16(float* c, const uint32_t* a, const uint32_t* b) {
    asm volatile(
        "mma.sync.aligned.m16n8k16.row.col.f32.f16.f16.f32 "
        "{%0,%1,%2,%3}, {%4,%5,%6,%7}, {%8,%9}, {%0,%1,%2,%3};"
        : "+f"(c[0]), "+f"(c[1]), "+f"(c[2]), "+f"(c[3])
        : "r"(a[0]), "r"(a[1]), "r"(a[2]), "r"(a[3]), "r"(b[0]), "r"(b[1]));
}
#define CP_ASYNC16(saddr, gaddr) \
    asm volatile("cp.async.cg.shared.global [%0], [%1], 16;" :: "r"(saddr), "l"(gaddr))
#define CP_COMMIT() asm volatile("cp.async.commit_group;")
#define CP_WAIT(n)  asm volatile("cp.async.wait_group %0;" :: "n"(n) : "memory")

// ---------------- fused prep: cvt x, cvt W, scatter ----------------
#define XBLOCKS (B_ROWS * DIN / 4 / 256)       // 8192
#define WBLOCKS (NE * DIN * DOUT / 4 / 256)    // 2048
#define SBLOCKS (B_ROWS / 256)                 // 64
#define PREP_GRID (XBLOCKS + WBLOCKS + SBLOCKS)

__global__ void prep_kernel(const float* __restrict__ x, const float* __restrict__ W,
                            const int* __restrict__ groups) {
    int bid = blockIdx.x;
    if (bid < XBLOCKS + WBLOCKS) {
        const float4* src;
        uint2* dst;
        int i;
        if (bid < XBLOCKS) {
            i = bid * blockDim.x + threadIdx.x;
            src = (const float4*)x;
            dst = (uint2*)g_xh;
        } else {
            i = (bid - XBLOCKS) * blockDim.x + threadIdx.x;
            src = (const float4*)W;
            dst = (uint2*)g_wh;
        }
        float4 v = src[i];
        __half2 h0 = __floats2half2_rn(v.x, v.y);
        __half2 h1 = __floats2half2_rn(v.z, v.w);
        dst[i] = make_uint2(*(uint32_t*)&h0, *(uint32_t*)&h1);
    } else {
        int b = (bid - XBLOCKS - WBLOCKS) * blockDim.x + threadIdx.x;
        int e = groups[b * GCOLS];
        int lane = threadIdx.x & 31;
        unsigned mask = __match_any_sync(0xffffffffu, e);
        int leader = __ffs(mask) - 1;
        int prefix = __popc(mask & ((1u << lane) - 1));
        int base = 0;
        if (lane == leader) base = atomicAdd(&g_fill[e], __popc(mask));
        base = __shfl_sync(0xffffffffu, base, leader);
        g_rowpad[e * B_ROWS + base + prefix] = b;
    }
}

// ---------------- persistent grouped GEMM: fp16, 128x128, NPIPE=4, self-reset ----------------
__global__ __launch_bounds__(256, 2)
void gemm_mma(const float* __restrict__ bias, float* __restrict__ out) {
    extern __shared__ char sm[];
    int* sm_w   = (int*)sm;
    int* s_cum  = (int*)(sm + 16);
    int* s_fill = (int*)(sm + 64);
    int* srows  = (int*)(sm + 256);
    const uint32_t smu = smem_u32(sm);

    const int tid  = threadIdx.x;
    const int lane = tid & 31;
    const int wid  = tid >> 5;

    if (tid < NE) s_fill[tid] = g_fill[tid];
    __syncthreads();
    if (tid == 0) {
        int c = 0;
        s_cum[0] = 0;
        for (int e = 0; e < NE; e++) {
            c += (s_fill[e] + TM - 1) / TM;
            s_cum[e + 1] = c;
        }
    }
    __syncthreads();
    const int nwork = s_cum[NE] * NCOLT;

    // warp compute coords: warp tile 32x64
    const int m0w = (wid >> 1) * 32;
    const int n0w = (wid & 1) * 64;
    const int lr = (lane & 7) + ((lane >> 3) & 1) * 8;
    const int lc = (lane >> 4) * 8;
    const int a_lm_base = ((m0w + lr) * SA + lc) * 2;
    const int b_lm_base = (lr * SB + n0w + lc) * 2;

    // cp.async slot shapes: A 2 chunks/thread, B 2 chunks/thread
    const int am0  = (tid + 0)   >> 2;
    const int am1  = (tid + 256) >> 2;
    const int asec = tid & 3;
    const uint32_t asw0 = smu + OFF_BUF + AOF + am0 * (SA * 2) + asec * 16;
    const uint32_t asw1 = smu + OFF_BUF + AOF + am1 * (SA * 2) + asec * 16;
    const int bk0 = (tid + 0) >> 4, bk1 = (tid + 256) >> 4;
    const int bsec = tid & 15;
    const uint32_t bsw0 = smu + OFF_BUF + BOF + bk0 * (SB * 2) + bsec * 16;
    const uint32_t bsw1 = smu + OFF_BUF + BOF + bk1 * (SB * 2) + bsec * 16;

    const int rl = lane >> 2;
    const int cl = (lane & 3) * 2;

    for (;;) {
        if (tid == 0) sm_w[0] = atomicAdd(&g_work, 1);
        __syncthreads();
        const int w = sm_w[0];
        if (w >= nwork) break;

        const int n0 = (w & (NCOLT - 1)) * TN;
        const int t  = w >> 2;
        int e = 0;
        while (t >= s_cum[e + 1]) e++;
        const int rowbase = (t - s_cum[e]) * TM;
        const int cnt  = s_fill[e];
        const int rows = (cnt - rowbase < TM) ? (cnt - rowbase) : TM;

        if (tid < TM) srows[tid] = (tid < rows) ? g_rowpad[e * B_ROWS + rowbase + tid] : -1;
        __syncthreads();

        int gr0 = srows[am0]; if (gr0 < 0) gr0 = 0;
        int gr1 = srows[am1]; if (gr1 < 0) gr1 = 0;
        const __half* ag0 = g_xh + (size_t)gr0 * DIN + asec * 8;
        const __half* ag1 = g_xh + (size_t)gr1 * DIN + asec * 8;
        const __half* bg0 = g_wh + ((size_t)e * DIN + bk0) * DOUT + n0 + bsec * 8;
        const __half* bg1 = g_wh + ((size_t)e * DIN + bk1) * DOUT + n0 + bsec * 8;

        float c[2][8][4];
#pragma unroll
        for (int mt = 0; mt < 2; mt++)
#pragma unroll
            for (int nt = 0; nt < 8; nt++)
#pragma unroll
                for (int j = 0; j < 4; j++) c[mt][nt][j] = 0.f;

        // prologue: stages 0..2
#pragma unroll
        for (int s = 0; s < NPIPE - 1; s++) {
            const uint32_t bo = s * BUF_BYTES;
            const int ka = s * TK;
            const size_t kb = (size_t)(s * TK) * DOUT;
            CP_ASYNC16(asw0 + bo, ag0 + ka);
            CP_ASYNC16(asw1 + bo, ag1 + ka);
            CP_ASYNC16(bsw0 + bo, bg0 + kb);
            CP_ASYNC16(bsw1 + bo, bg1 + kb);
            CP_COMMIT();
        }

        int slot = 0, fslot = NPIPE - 1;
        for (int kt = 0; kt < NSTAGE; kt++) {
            CP_WAIT(NPIPE - 2);
            __syncthreads();

            if (kt + NPIPE - 1 < NSTAGE) {
                const uint32_t bo = fslot * BUF_BYTES;
                const int ka = (kt + NPIPE - 1) * TK;
                const size_t kb = (size_t)((kt + NPIPE - 1) * TK) * DOUT;
                CP_ASYNC16(asw0 + bo, ag0 + ka);
                CP_ASYNC16(asw1 + bo, ag1 + ka);
                CP_ASYNC16(bsw0 + bo, bg0 + kb);
                CP_ASYNC16(bsw1 + bo, bg1 + kb);
            }
            CP_COMMIT();

            const uint32_t bb = smu + OFF_BUF + slot * BUF_BYTES;

            // --- k-step 0: issue all ldsm, then MMAs; B of k-step 1 hoisted ---
            uint32_t ah[2][4], bh[4][4], bh2[4][4];
#pragma unroll
            for (int mt = 0; mt < 2; mt++)
                ldsm_x4(ah[mt], bb + a_lm_base + (mt * 16 * SA) * 2 + AOF);
#pragma unroll
            for (int p = 0; p < 4; p++)
                ldsm_x4_t(bh[p], bb + b_lm_base + (p * 16) * 2 + BOF);
            // hoist k-step 1 B loads to overlap with k-step 0 MMAs
#pragma unroll
            for (int p = 0; p < 4; p++)
                ldsm_x4_t(bh2[p], bb + b_lm_base + (16 * SB + p * 16) * 2 + BOF);
#pragma unroll
            for (int mt = 0; mt < 2; mt++)
#pragma unroll
                for (int p = 0; p < 4; p++) {
                    mma_f16(c[mt][2 * p],     ah[mt], &bh[p][0]);
                    mma_f16(c[mt][2 * p + 1], ah[mt], &bh[p][2]);
                }

            // --- k-step 1 ---
#pragma unroll
            for (int mt = 0; mt < 2; mt++)
                ldsm_x4(ah[mt], bb + a_lm_base + (mt * 16 * SA + 16) * 2 + AOF);
#pragma unroll
            for (int mt = 0; mt < 2; mt++)
#pragma unroll
                for (int p = 0; p < 4; p++) {
                    mma_f16(c[mt][2 * p],     ah[mt], &bh2[p][0]);
                    mma_f16(c[mt][2 * p + 1], ah[mt], &bh2[p][2]);
                }

            slot  = (slot  + 1 == NPIPE) ? 0 : slot + 1;
            fslot = (fslot + 1 == NPIPE) ? 0 : fslot + 1;
        }

        // epilogue: bias + scattered stores
#pragma unroll
        for (int mt = 0; mt < 2; mt++) {
            const int lm0 = m0w + mt * 16 + rl;
            const int r0 = srows[lm0];
            const int r1 = srows[lm0 + 8];
#pragma unroll
            for (int nt = 0; nt < 8; nt++) {
                const int gcol = n0 + n0w + nt * 8 + cl;
                const float2 bv2 = *(const float2*)(bias + e * DOUT + gcol);
                if (r0 >= 0) {
                    float2 v = make_float2(c[mt][nt][0] + bv2.x, c[mt][nt][1] + bv2.y);
                    *(float2*)(out + (size_t)r0 * DOUT + gcol) = v;
                }
                if (r1 >= 0) {
                    float2 v = make_float2(c[mt][nt][2] + bv2.x, c[mt][nt][3] + bv2.y);
                    *(float2*)(out + (size_t)r1 * DOUT + gcol) = v;
                }
            }
        }
    }

    // self-reset for next replay
    __syncthreads();
    if (tid == 0) {
        int prev = atomicAdd(&g_done, 1);
        if (prev == GEMM_GRID - 1) {
#pragma unroll
            for (int i = 0; i < NE; i++) g_fill[i] = 0;
            g_work = 0;
            g_done = 0;
            __threadfence();
        }
    }
}

// ---------------- launch ----------------
extern "C" void kernel_launch(void* const* d_in, const int* in_sizes, int n_in,
                              void* d_out, int out_size) {
    const float* x      = (const float*)d_in[0];
    const int*   groups = (const int*)d_in[1];
    const float* W      = (const float*)d_in[2];
    const float* bias   = (const float*)d_in[3];
    float*       out    = (float*)d_out;

    cudaFuncSetAttribute(gemm_mma, cudaFuncAttributeMaxDynamicSharedMemorySize, GEMM_SMEM);

    prep_kernel<<<PREP_GRID, 256>>>(x, W, groups);
    gemm_mma<<<GEMM_GRID, 256, GEMM_SMEM>>>(bias, out);
}

// round 11
// speedup vs baseline: 1.1306x; 1.0100x over previous
#include <cuda_runtime.h>
#include <cuda_fp16.h>
#include <cstdint>

// ---------------- problem constants ----------------
#define B_ROWS 16384
#define DIN 512
#define DOUT 512
#define NE 8
#define GCOLS 2

// ---------------- GEMM tiling ----------------
#define TM 128
#define TN 128
#define TK 64
#define NSTAGE (DIN / TK)          // 8
#define NCOLT (DOUT / TN)          // 4

#define SA 72    // A smem row stride (halves): 144B = 9 granules (odd -> conflict-free)
#define SB 136   // B smem row stride (halves): 272B = 17 granules

#define AOF 0
#define BOF (TM * SA * 2)                     // 18432
#define BUF_BYTES (TM * SA * 2 + TK * SB * 2) // 35840
#define OFF_BUF 1024
#define GEMM_SMEM (OFF_BUF + 2 * BUF_BYTES)   // 72704 -> 2 CTAs/SM

#define GEMM_GRID 304   // 2 CTAs/SM x 152 SMs, all co-resident

// ---------------- device scratch ----------------
__device__ int g_fill[NE];       // zero at start; self-reset by gemm
__device__ int g_work;
__device__ int g_done;
__device__ int g_rowpad[NE * B_ROWS];

__device__ __align__(16) __half g_xh[B_ROWS * DIN];      // 16MB
__device__ __align__(16) __half g_wh[NE * DIN * DOUT];   // 4MB, [e][k][n]

// ---------------- helpers ----------------
__device__ __forceinline__ uint32_t smem_u32(const void* p) {
    uint32_t a;
    asm("{ .reg .u64 t; cvta.to.shared.u64 t, %1; cvt.u32.u64 %0, t; }" : "=r"(a) : "l"(p));
    return a;
}
__device__ __forceinline__ void ldsm_x4(uint32_t* r, uint32_t addr) {
    asm volatile("ldmatrix.sync.aligned.m8n8.x4.shared.b16 {%0,%1,%2,%3}, [%4];"
                 : "=r"(r[0]), "=r"(r[1]), "=r"(r[2]), "=r"(r[3]) : "r"(addr));
}
__device__ __forceinline__ void ldsm_x4_t(uint32_t* r, uint32_t addr) {
    asm volatile("ldmatrix.sync.aligned.m8n8.x4.trans.shared.b16 {%0,%1,%2,%3}, [%4];"
                 : "=r"(r[0]), "=r"(r[1]), "=r"(r[2]), "=r"(r[3]) : "r"(addr));
}
__device__ __forceinline__ void mma_f16(float* c, const uint32_t* a, const uint32_t* b) {
    asm volatile(
        "mma.sync.aligned.m16n8k16.row.col.f32.f16.f16.f32 "
        "{%0,%1,%2,%3}, {%4,%5,%6,%7}, {%8,%9}, {%0,%1,%2,%3};"
        : "+f"(c[0]), "+f"(c[1]), "+f"(c[2]), "+f"(c[3])
        : "r"(a[0]), "r"(a[1]), "r"(a[2]), "r"(a[3]), "r"(b[0]), "r"(b[1]));
}
#define CP_ASYNC16(saddr, gaddr) \
    asm volatile("cp.async.cg.shared.global [%0], [%1], 16;" :: "r"(saddr), "l"(gaddr))
#define CP_COMMIT() asm volatile("cp.async.commit_group;")
#define CP_WAIT0()  asm volatile("cp.async.wait_group 0;" ::: "memory")

// ---------------- fused prep: cvt x, cvt W, scatter ----------------
#define XBLOCKS (B_ROWS * DIN / 4 / 256)       // 8192
#define WBLOCKS (NE * DIN * DOUT / 4 / 256)    // 2048
#define SBLOCKS (B_ROWS / 256)                 // 64
#define PREP_GRID (XBLOCKS + WBLOCKS + SBLOCKS)

__global__ void prep_kernel(const float* __restrict__ x, const float* __restrict__ W,
                            const int* __restrict__ groups) {
    int bid = blockIdx.x;
    if (bid < XBLOCKS + WBLOCKS) {
        const float4* src;
        uint2* dst;
        int i;
        if (bid < XBLOCKS) {
            i = bid * blockDim.x + threadIdx.x;
            src = (const float4*)x;
            dst = (uint2*)g_xh;
        } else {
            i = (bid - XBLOCKS) * blockDim.x + threadIdx.x;
            src = (const float4*)W;
            dst = (uint2*)g_wh;
        }
        float4 v = src[i];
        __half2 h0 = __floats2half2_rn(v.x, v.y);
        __half2 h1 = __floats2half2_rn(v.z, v.w);
        dst[i] = make_uint2(*(uint32_t*)&h0, *(uint32_t*)&h1);
    } else {
        int b = (bid - XBLOCKS - WBLOCKS) * blockDim.x + threadIdx.x;
        int e = groups[b * GCOLS];
        int lane = threadIdx.x & 31;
        unsigned mask = __match_any_sync(0xffffffffu, e);
        int leader = __ffs(mask) - 1;
        int prefix = __popc(mask & ((1u << lane) - 1));
        int base = 0;
        if (lane == leader) base = atomicAdd(&g_fill[e], __popc(mask));
        base = __shfl_sync(0xffffffffu, base, leader);
        g_rowpad[e * B_ROWS + base + prefix] = b;
    }
}

// ---------------- persistent grouped GEMM: fp16, TK=64 double-buffer ----------------
__global__ __launch_bounds__(256, 2)
void gemm_mma(const float* __restrict__ bias, float* __restrict__ out) {
    extern __shared__ char sm[];
    int* sm_w   = (int*)sm;
    int* s_cum  = (int*)(sm + 16);
    int* s_fill = (int*)(sm + 64);
    int* srows  = (int*)(sm + 256);
    const uint32_t smu = smem_u32(sm);

    const int tid  = threadIdx.x;
    const int lane = tid & 31;
    const int wid  = tid >> 5;

    if (tid < NE) s_fill[tid] = g_fill[tid];
    __syncthreads();
    if (tid == 0) {
        int c = 0;
        s_cum[0] = 0;
        for (int e = 0; e < NE; e++) {
            c += (s_fill[e] + TM - 1) / TM;
            s_cum[e + 1] = c;
        }
    }
    __syncthreads();
    const int nwork = s_cum[NE] * NCOLT;

    // warp compute coords: warp tile 32x64
    const int m0w = (wid >> 1) * 32;
    const int n0w = (wid & 1) * 64;
    const int lr = (lane & 7) + ((lane >> 3) & 1) * 8;
    const int lc = (lane >> 4) * 8;
    const int a_lm_base = ((m0w + lr) * SA + lc) * 2;
    const int b_lm_base = (lr * SB + n0w + lc) * 2;

    // cp.async slot shapes: 4 A chunks + 4 B chunks per thread per stage
    // A: 128 rows x 8 sectors (16B) = 1024 chunks
    int am[4];
    uint32_t asw[4];
#pragma unroll
    for (int t = 0; t < 4; t++) {
        int c = tid + t * 256;
        am[t] = c >> 3;
        int sec = c & 7;
        asw[t] = smu + OFF_BUF + AOF + am[t] * (SA * 2) + sec * 16;
    }
    const int asec = tid & 7;
    // B: 64 k-rows x 16 sectors = 1024 chunks
    int bk[4];
    uint32_t bsw[4];
#pragma unroll
    for (int t = 0; t < 4; t++) {
        int c = tid + t * 256;
        bk[t] = c >> 4;
        int sec = c & 15;
        bsw[t] = smu + OFF_BUF + BOF + bk[t] * (SB * 2) + sec * 16;
    }
    const int bsec = tid & 15;

    const int rl = lane >> 2;
    const int cl = (lane & 3) * 2;

    for (;;) {
        if (tid == 0) sm_w[0] = atomicAdd(&g_work, 1);
        __syncthreads();
        const int w = sm_w[0];
        if (w >= nwork) break;

        const int n0 = (w & (NCOLT - 1)) * TN;
        const int t  = w >> 2;
        int e = 0;
        while (t >= s_cum[e + 1]) e++;
        const int rowbase = (t - s_cum[e]) * TM;
        const int cnt  = s_fill[e];
        const int rows = (cnt - rowbase < TM) ? (cnt - rowbase) : TM;

        if (tid < TM) srows[tid] = (tid < rows) ? g_rowpad[e * B_ROWS + rowbase + tid] : -1;
        __syncthreads();

        const __half* ag[4];
#pragma unroll
        for (int tt = 0; tt < 4; tt++) {
            int gr = srows[am[tt]]; if (gr < 0) gr = 0;
            ag[tt] = g_xh + (size_t)gr * DIN + asec * 8;
        }
        const __half* bg[4];
#pragma unroll
        for (int tt = 0; tt < 4; tt++)
            bg[tt] = g_wh + ((size_t)e * DIN + bk[tt]) * DOUT + n0 + bsec * 8;

        float c[2][8][4];
#pragma unroll
        for (int mt = 0; mt < 2; mt++)
#pragma unroll
            for (int nt = 0; nt < 8; nt++)
#pragma unroll
                for (int j = 0; j < 4; j++) c[mt][nt][j] = 0.f;

        // prologue: fill stage 0 into buffer 0
#pragma unroll
        for (int tt = 0; tt < 4; tt++) CP_ASYNC16(asw[tt], ag[tt]);
#pragma unroll
        for (int tt = 0; tt < 4; tt++) CP_ASYNC16(bsw[tt], bg[tt]);
        CP_COMMIT();

        for (int kt = 0; kt < NSTAGE; kt++) {
            CP_WAIT0();
            __syncthreads();

            // fill next stage into the other buffer (hidden under compute)
            if (kt + 1 < NSTAGE) {
                const uint32_t bo = ((kt + 1) & 1) * BUF_BYTES;
                const int ka = (kt + 1) * TK;
                const size_t kb = (size_t)((kt + 1) * TK) * DOUT;
#pragma unroll
                for (int tt = 0; tt < 4; tt++) CP_ASYNC16(asw[tt] + bo, ag[tt] + ka);
#pragma unroll
                for (int tt = 0; tt < 4; tt++) CP_ASYNC16(bsw[tt] + bo, bg[tt] + kb);
            }
            CP_COMMIT();

            const uint32_t bb = smu + OFF_BUF + (kt & 1) * BUF_BYTES;
#pragma unroll
            for (int ks = 0; ks < 4; ks++) {
                const int kso = ks * 16;
                uint32_t ah[2][4];
#pragma unroll
                for (int mt = 0; mt < 2; mt++)
                    ldsm_x4(ah[mt], bb + a_lm_base + (mt * 16 * SA + kso) * 2 + AOF);
                uint32_t bh[4][4];
#pragma unroll
                for (int p = 0; p < 4; p++)
                    ldsm_x4_t(bh[p], bb + b_lm_base + (kso * SB + p * 16) * 2 + BOF);
#pragma unroll
                for (int mt = 0; mt < 2; mt++)
#pragma unroll
                    for (int p = 0; p < 4; p++) {
                        mma_f16(c[mt][2 * p],     ah[mt], &bh[p][0]);
                        mma_f16(c[mt][2 * p + 1], ah[mt], &bh[p][2]);
                    }
            }
        }

        // epilogue: bias + scattered stores
#pragma unroll
        for (int mt = 0; mt < 2; mt++) {
            const int lm0 = m0w + mt * 16 + rl;
            const int r0 = srows[lm0];
            const int r1 = srows[lm0 + 8];
#pragma unroll
            for (int nt = 0; nt < 8; nt++) {
                const int gcol = n0 + n0w + nt * 8 + cl;
                const float2 bv2 = *(const float2*)(bias + e * DOUT + gcol);
                if (r0 >= 0) {
                    float2 v = make_float2(c[mt][nt][0] + bv2.x, c[mt][nt][1] + bv2.y);
                    *(float2*)(out + (size_t)r0 * DOUT + gcol) = v;
                }
                if (r1 >= 0) {
                    float2 v = make_float2(c[mt][nt][2] + bv2.x, c[mt][nt][3] + bv2.y);
                    *(float2*)(out + (size_t)r1 * DOUT + gcol) = v;
                }
            }
        }
        __syncthreads();   // srows stable until all warps finish epilogue
    }

    // self-reset for next replay
    __syncthreads();
    if (tid == 0) {
        int prev = atomicAdd(&g_done, 1);
        if (prev == GEMM_GRID - 1) {
#pragma unroll
            for (int i = 0; i < NE; i++) g_fill[i] = 0;
            g_work = 0;
            g_done = 0;
            __threadfence();
        }
    }
}

// ---------------- launch ----------------
extern "C" void kernel_launch(void* const* d_in, const int* in_sizes, int n_in,
                              void* d_out, int out_size) {
    const float* x      = (const float*)d_in[0];
    const int*   groups = (const int*)d_in[1];
    const float* W      = (const float*)d_in[2];
    const float* bias   = (const float*)d_in[3];
    float*       out    = (float*)d_out;

    cudaFuncSetAttribute(gemm_mma, cudaFuncAttributeMaxDynamicSharedMemorySize, GEMM_SMEM);

    prep_kernel<<<PREP_GRID, 256>>>(x, W, groups);
    gemm_mma<<<GEMM_GRID, 256, GEMM_SMEM>>>(bias, out);
}

// round 12
// speedup vs baseline: 1.2264x; 1.0847x over previous
#include <cuda_runtime.h>
#include <cuda_fp16.h>
#include <cstdint>

// ---------------- problem constants ----------------
#define B_ROWS 16384
#define DIN 512
#define DOUT 512
#define NE 8
#define GCOLS 2

// ---------------- GEMM tiling ----------------
#define TM 128
#define TN 128
#define TK 64
#define NSTAGE (DIN / TK)          // 8
#define NCOLT (DOUT / TN)          // 4

#define SA 72    // A16 smem row stride (halves): 144B = 9 granules (odd -> conflict-free)
#define SB 136   // B smem row stride (halves): 272B

// smem layout (bytes, per CTA)
#define A32OF 1024                      // fp32 A staging, LINEAR 128x64 floats
#define A32BYTES 32768
#define A16OF (A32OF + A32BYTES)        // 33792; two fp16 A buffers
#define A16BUF (TM * SA * 2)            // 18432
#define B16OF (A16OF + 2 * A16BUF)      // 70656; two fp16 B buffers
#define B16BUF (TK * SB * 2)            // 17408
#define GEMM_SMEM (B16OF + 2 * B16BUF)  // 105472 -> 2 CTAs/SM (211KB <= 228KB)

#define GEMM_GRID 304   // 2 CTAs/SM x 152 SMs, all co-resident

// ---------------- device scratch ----------------
__device__ int g_fill[NE];       // zero at start; self-reset by gemm
__device__ int g_work;
__device__ int g_done;
__device__ int g_rowpad[NE * B_ROWS];

__device__ __align__(16) __half g_wh[NE * DIN * DOUT];   // 4MB, [e][k][n]

// ---------------- helpers ----------------
__device__ __forceinline__ uint32_t smem_u32(const void* p) {
    uint32_t a;
    asm("{ .reg .u64 t; cvta.to.shared.u64 t, %1; cvt.u32.u64 %0, t; }" : "=r"(a) : "l"(p));
    return a;
}
__device__ __forceinline__ void ldsm_x4(uint32_t* r, uint32_t addr) {
    asm volatile("ldmatrix.sync.aligned.m8n8.x4.shared.b16 {%0,%1,%2,%3}, [%4];"
                 : "=r"(r[0]), "=r"(r[1]), "=r"(r[2]), "=r"(r[3]) : "r"(addr));
}
__device__ __forceinline__ void ldsm_x4_t(uint32_t* r, uint32_t addr) {
    asm volatile("ldmatrix.sync.aligned.m8n8.x4.trans.shared.b16 {%0,%1,%2,%3}, [%4];"
                 : "=r"(r[0]), "=r"(r[1]), "=r"(r[2]), "=r"(r[3]) : "r"(addr));
}
__device__ __forceinline__ void mma_f16(float* c, const uint32_t* a, const uint32_t* b) {
    asm volatile(
        "mma.sync.aligned.m16n8k16.row.col.f32.f16.f16.f32 "
        "{%0,%1,%2,%3}, {%4,%5,%6,%7}, {%8,%9}, {%0,%1,%2,%3};"
        : "+f"(c[0]), "+f"(c[1]), "+f"(c[2]), "+f"(c[3])
        : "r"(a[0]), "r"(a[1]), "r"(a[2]), "r"(a[3]), "r"(b[0]), "r"(b[1]));
}
#define CP_ASYNC16(saddr, gaddr) \
    asm volatile("cp.async.cg.shared.global [%0], [%1], 16;" :: "r"(saddr), "l"(gaddr))
#define CP_COMMIT() asm volatile("cp.async.commit_group;")
#define CP_WAIT0()  asm volatile("cp.async.wait_group 0;" ::: "memory")

// ---------------- prep: cvt W (x handled in-GEMM), scatter ----------------
#define WBLOCKS (NE * DIN * DOUT / 4 / 256)    // 2048
#define SBLOCKS (B_ROWS / 256)                 // 64
#define PREP_GRID (WBLOCKS + SBLOCKS)

__global__ void prep_kernel(const float* __restrict__ W, const int* __restrict__ groups) {
    int bid = blockIdx.x;
    if (bid < WBLOCKS) {
        int i = bid * blockDim.x + threadIdx.x;
        float4 v = ((const float4*)W)[i];
        __half2 h0 = __floats2half2_rn(v.x, v.y);
        __half2 h1 = __floats2half2_rn(v.z, v.w);
        ((uint2*)g_wh)[i] = make_uint2(*(uint32_t*)&h0, *(uint32_t*)&h1);
    } else {
        int b = (bid - WBLOCKS) * blockDim.x + threadIdx.x;
        int e = groups[b * GCOLS];
        int lane = threadIdx.x & 31;
        unsigned mask = __match_any_sync(0xffffffffu, e);
        int leader = __ffs(mask) - 1;
        int prefix = __popc(mask & ((1u << lane) - 1));
        int base = 0;
        if (lane == leader) base = atomicAdd(&g_fill[e], __popc(mask));
        base = __shfl_sync(0xffffffffu, base, leader);
        g_rowpad[e * B_ROWS + base + prefix] = b;
    }
}

// ---------------- persistent grouped GEMM: fused x fp32->fp16 convert ----------------
__global__ __launch_bounds__(256, 2)
void gemm_mma(const float* __restrict__ x, const float* __restrict__ bias,
              float* __restrict__ out) {
    extern __shared__ char sm[];
    int* sm_w   = (int*)sm;
    int* s_cum  = (int*)(sm + 16);
    int* s_fill = (int*)(sm + 64);
    int* srows  = (int*)(sm + 256);
    const uint32_t smu = smem_u32(sm);

    const int tid  = threadIdx.x;
    const int lane = tid & 31;
    const int wid  = tid >> 5;

    if (tid < NE) s_fill[tid] = g_fill[tid];
    __syncthreads();
    if (tid == 0) {
        int c = 0;
        s_cum[0] = 0;
        for (int e = 0; e < NE; e++) {
            c += (s_fill[e] + TM - 1) / TM;
            s_cum[e + 1] = c;
        }
    }
    __syncthreads();
    const int nwork = s_cum[NE] * NCOLT;

    // warp compute coords: warp tile 32x64
    const int m0w = (wid >> 1) * 32;
    const int n0w = (wid & 1) * 64;
    const int lr = (lane & 7) + ((lane >> 3) & 1) * 8;
    const int lc = (lane >> 4) * 8;
    const int a_lm_base = ((m0w + lr) * SA + lc) * 2;
    const int b_lm_base = (lr * SB + n0w + lc) * 2;

    // A fp32 cp.async: 8 x 16B chunks/thread/stage, LINEAR layout
    // chunk c = tid + t*256: row m = c>>4, sector = c&15 (16 floats-worth = 4 floats each)
    const int asec4 = (tid & 15) * 4;             // float offset within row
    const uint32_t a32base = smu + A32OF + tid * 16;
    // convert-pass per-thread dst offset in A16 buffer
    const uint32_t cvt_off = (tid >> 4) * 144 + (tid & 15) * 8;

    // B fp16 cp.async: 4 chunks/thread/stage
    int bk[4];
    uint32_t bso[4];
#pragma unroll
    for (int t = 0; t < 4; t++) {
        int c = tid + t * 256;
        bk[t] = c >> 4;
        bso[t] = smu + B16OF + bk[t] * (SB * 2) + (c & 15) * 16;
    }
    const int bsec = tid & 15;

    const int rl = lane >> 2;
    const int cl = (lane & 3) * 2;

    for (;;) {
        if (tid == 0) sm_w[0] = atomicAdd(&g_work, 1);
        __syncthreads();
        const int w = sm_w[0];
        if (w >= nwork) break;

        const int n0 = (w & (NCOLT - 1)) * TN;
        const int t  = w >> 2;
        int e = 0;
        while (t >= s_cum[e + 1]) e++;
        const int rowbase = (t - s_cum[e]) * TM;
        const int cnt  = s_fill[e];
        const int rows = (cnt - rowbase < TM) ? (cnt - rowbase) : TM;

        if (tid < TM) srows[tid] = (tid < rows) ? g_rowpad[e * B_ROWS + rowbase + tid] : -1;
        __syncthreads();

        // A row pointers for the 8 chunks (rows (tid>>4) + t*16)
        const float* agp[8];
#pragma unroll
        for (int tt = 0; tt < 8; tt++) {
            int gr = srows[(tid >> 4) + tt * 16];
            if (gr < 0) gr = 0;
            agp[tt] = x + (size_t)gr * DIN + asec4;
        }
        const __half* bg[4];
#pragma unroll
        for (int tt = 0; tt < 4; tt++)
            bg[tt] = g_wh + ((size_t)e * DIN + bk[tt]) * DOUT + n0 + bsec * 8;

        float c[2][8][4];
#pragma unroll
        for (int mt = 0; mt < 2; mt++)
#pragma unroll
            for (int nt = 0; nt < 8; nt++)
#pragma unroll
                for (int j = 0; j < 4; j++) c[mt][nt][j] = 0.f;

        // prologue: fill stage 0 (A fp32 + B fp16 buf0)
#pragma unroll
        for (int tt = 0; tt < 8; tt++) CP_ASYNC16(a32base + tt * 4096, agp[tt]);
#pragma unroll
        for (int tt = 0; tt < 4; tt++) CP_ASYNC16(bso[tt], bg[tt]);
        CP_COMMIT();

        for (int kt = 0; kt < NSTAGE; kt++) {
            CP_WAIT0();
            __syncthreads();          // A32(kt), B[kt&1] ready

            // ---- convert A32 (fp32 linear) -> A16[kt&1] (ldsm layout) ----
            const uint32_t a16b = smu + A16OF + (kt & 1) * A16BUF;
#pragma unroll
            for (int k = 0; k < 8; k++) {
                float4 v;
                asm volatile("ld.shared.v4.f32 {%0,%1,%2,%3}, [%4];"
                    : "=f"(v.x), "=f"(v.y), "=f"(v.z), "=f"(v.w)
                    : "r"(a32base + k * 4096));
                uint32_t h0, h1;
                asm volatile("cvt.rn.f16x2.f32 %0, %1, %2;" : "=r"(h0) : "f"(v.y), "f"(v.x));
                asm volatile("cvt.rn.f16x2.f32 %0, %1, %2;" : "=r"(h1) : "f"(v.w), "f"(v.z));
                asm volatile("st.shared.v2.u32 [%0], {%1,%2};"
                    :: "r"(a16b + cvt_off + k * 2304), "r"(h0), "r"(h1) : "memory");
            }
            __syncthreads();          // A16 ready; A32 free for refill

            // ---- prefetch stage kt+1 ----
            if (kt + 1 < NSTAGE) {
                const int ka = (kt + 1) * TK;
                const size_t kb = (size_t)((kt + 1) * TK) * DOUT;
                const uint32_t bbo = ((kt + 1) & 1) * B16BUF;
#pragma unroll
                for (int tt = 0; tt < 8; tt++) CP_ASYNC16(a32base + tt * 4096, agp[tt] + ka);
#pragma unroll
                for (int tt = 0; tt < 4; tt++) CP_ASYNC16(bso[tt] + bbo, bg[tt] + kb);
            }
            CP_COMMIT();

            // ---- MMA on A16[kt&1], B[kt&1] ----
            const uint32_t ab = a16b;
            const uint32_t bb = smu + B16OF + (kt & 1) * B16BUF;
#pragma unroll
            for (int ks = 0; ks < 4; ks++) {
                const int kso = ks * 16;
                uint32_t ah[2][4];
#pragma unroll
                for (int mt = 0; mt < 2; mt++)
                    ldsm_x4(ah[mt], ab + a_lm_base + (mt * 16 * SA + kso) * 2);
                uint32_t bh[4][4];
#pragma unroll
                for (int p = 0; p < 4; p++)
                    ldsm_x4_t(bh[p], bb + b_lm_base + (kso * SB + p * 16) * 2);
#pragma unroll
                for (int mt = 0; mt < 2; mt++)
#pragma unroll
                    for (int p = 0; p < 4; p++) {
                        mma_f16(c[mt][2 * p],     ah[mt], &bh[p][0]);
                        mma_f16(c[mt][2 * p + 1], ah[mt], &bh[p][2]);
                    }
            }
        }

        // epilogue: bias + scattered stores
#pragma unroll
        for (int mt = 0; mt < 2; mt++) {
            const int lm0 = m0w + mt * 16 + rl;
            const int r0 = srows[lm0];
            const int r1 = srows[lm0 + 8];
#pragma unroll
            for (int nt = 0; nt < 8; nt++) {
                const int gcol = n0 + n0w + nt * 8 + cl;
                const float2 bv2 = *(const float2*)(bias + e * DOUT + gcol);
                if (r0 >= 0) {
                    float2 v = make_float2(c[mt][nt][0] + bv2.x, c[mt][nt][1] + bv2.y);
                    *(float2*)(out + (size_t)r0 * DOUT + gcol) = v;
                }
                if (r1 >= 0) {
                    float2 v = make_float2(c[mt][nt][2] + bv2.x, c[mt][nt][3] + bv2.y);
                    *(float2*)(out + (size_t)r1 * DOUT + gcol) = v;
                }
            }
        }
        __syncthreads();   // srows stable until all warps finish epilogue
    }

    // self-reset for next replay
    __syncthreads();
    if (tid == 0) {
        int prev = atomicAdd(&g_done, 1);
        if (prev == GEMM_GRID - 1) {
#pragma unroll
            for (int i = 0; i < NE; i++) g_fill[i] = 0;
            g_work = 0;
            g_done = 0;
            __threadfence();
        }
    }
}

// ---------------- launch ----------------
extern "C" void kernel_launch(void* const* d_in, const int* in_sizes, int n_in,
                              void* d_out, int out_size) {
    const float* x      = (const float*)d_in[0];
    const int*   groups = (const int*)d_in[1];
    const float* W      = (const float*)d_in[2];
    const float* bias   = (const float*)d_in[3];
    float*       out    = (float*)d_out;

    cudaFuncSetAttribute(gemm_mma, cudaFuncAttributeMaxDynamicSharedMemorySize, GEMM_SMEM);

    prep_kernel<<<PREP_GRID, 256>>>(W, groups);
    gemm_mma<<<GEMM_GRID, 256, GEMM_SMEM>>>(x, bias, out);
}